// round 8
// baseline (speedup 1.0000x reference)
#include <cuda_runtime.h>
#include <math.h>

#define BB 64
#define PP 512
#define NN 512
#define EE 128
#define FFD 512
#define LLAYERS 6
#define M_TOT (BB*NN)
#define EPS 1e-5f
#define INV_SQRT_E 0.08838834764831845f  /* 1/sqrt(128) */

// ---------------- scratch (static device globals; no alloc allowed) ----------------
__device__ float g_x  [BB*NN*EE];
__device__ float g_y  [BB*NN*EE];
__device__ float g_h  [BB*NN*EE];
__device__ float g_sq [BB*NN*EE];
__device__ float g_ek [BB*NN*EE];
__device__ float g_ekv[BB*NN*EE];
__device__ float g_hid[BB*NN*FFD];
__device__ float g_aft[BB*PP*EE];
__device__ float g_gq [BB*EE];
__device__ float g_gm [BB*EE];

// ================= tf32 split helpers =================
__device__ __forceinline__ float2 split2(float x) {
    unsigned u; asm("cvt.rna.tf32.f32 %0,%1;" : "=r"(u) : "f"(x));
    float hi = __uint_as_float(u);
    return make_float2(hi, x - hi);
}

#define MMA8(d, a, b0, b1)                                                  \
    asm volatile("mma.sync.aligned.m16n8k8.row.col.f32.tf32.tf32.f32 "      \
        "{%0,%1,%2,%3},{%4,%5,%6,%7},{%8,%9},{%0,%1,%2,%3};"                \
        : "+f"(d[0]), "+f"(d[1]), "+f"(d[2]), "+f"(d[3])                    \
        : "r"(a[0]), "r"(a[1]), "r"(a[2]), "r"(a[3]), "r"(b0), "r"(b1))

// warp compute: 32x64 warp tile over BM=128 x BN=128 block, BK=16 smem tiles
// As: [16][132] float2 (k-major, hi/lo), Bs: [16][132] float2
__device__ __forceinline__ void mma_tile_128(
        const float2* __restrict__ As, const float2* __restrict__ Bs,
        float d[2][8][4], int wr0, int wc0, int qr, int qc) {
    #pragma unroll
    for (int kb = 0; kb < 16; kb += 8) {
        unsigned ah[2][4], al[2][4];
        #pragma unroll
        for (int i = 0; i < 2; i++) {
            const float2* p0 = As + (kb+qc)*132   + wr0 + i*16 + qr;
            const float2* p1 = As + (kb+qc+4)*132 + wr0 + i*16 + qr;
            float2 x0 = p0[0], x1 = p0[8], x2 = p1[0], x3 = p1[8];
            ah[i][0]=__float_as_uint(x0.x); al[i][0]=__float_as_uint(x0.y);
            ah[i][1]=__float_as_uint(x1.x); al[i][1]=__float_as_uint(x1.y);
            ah[i][2]=__float_as_uint(x2.x); al[i][2]=__float_as_uint(x2.y);
            ah[i][3]=__float_as_uint(x3.x); al[i][3]=__float_as_uint(x3.y);
        }
        #pragma unroll
        for (int j = 0; j < 8; j++) {
            int col = wc0 + j*8 + qr;
            float2 y0 = Bs[(kb+qc)*132 + col];
            float2 y1 = Bs[(kb+qc+4)*132 + col];
            unsigned bh0=__float_as_uint(y0.x), bl0=__float_as_uint(y0.y);
            unsigned bh1=__float_as_uint(y1.x), bl1=__float_as_uint(y1.y);
            #pragma unroll
            for (int i = 0; i < 2; i++) {
                MMA8(d[i][j], ah[i], bh0, bh1);
                MMA8(d[i][j], al[i], bh0, bh1);
                MMA8(d[i][j], ah[i], bl0, bl1);
            }
        }
    }
}

// warp compute: 32x32 warp tile, BN=64 block, two B matrices (num/den)
// As: [16][132] float2, Bs1/Bs2: [16][68] float2
__device__ __forceinline__ void mma_tile_64x2(
        const float2* __restrict__ As,
        const float2* __restrict__ Bs1, const float2* __restrict__ Bs2,
        float d1[2][4][4], float d2[2][4][4], int wr0, int wc0, int qr, int qc) {
    #pragma unroll
    for (int kb = 0; kb < 16; kb += 8) {
        unsigned ah[2][4], al[2][4];
        #pragma unroll
        for (int i = 0; i < 2; i++) {
            const float2* p0 = As + (kb+qc)*132   + wr0 + i*16 + qr;
            const float2* p1 = As + (kb+qc+4)*132 + wr0 + i*16 + qr;
            float2 x0 = p0[0], x1 = p0[8], x2 = p1[0], x3 = p1[8];
            ah[i][0]=__float_as_uint(x0.x); al[i][0]=__float_as_uint(x0.y);
            ah[i][1]=__float_as_uint(x1.x); al[i][1]=__float_as_uint(x1.y);
            ah[i][2]=__float_as_uint(x2.x); al[i][2]=__float_as_uint(x2.y);
            ah[i][3]=__float_as_uint(x3.x); al[i][3]=__float_as_uint(x3.y);
        }
        #pragma unroll
        for (int j = 0; j < 4; j++) {
            int col = wc0 + j*8 + qr;
            {
                float2 y0 = Bs1[(kb+qc)*68 + col];
                float2 y1 = Bs1[(kb+qc+4)*68 + col];
                unsigned bh0=__float_as_uint(y0.x), bl0=__float_as_uint(y0.y);
                unsigned bh1=__float_as_uint(y1.x), bl1=__float_as_uint(y1.y);
                #pragma unroll
                for (int i = 0; i < 2; i++) {
                    MMA8(d1[i][j], ah[i], bh0, bh1);
                    MMA8(d1[i][j], al[i], bh0, bh1);
                    MMA8(d1[i][j], ah[i], bl0, bl1);
                }
            }
            {
                float2 y0 = Bs2[(kb+qc)*68 + col];
                float2 y1 = Bs2[(kb+qc+4)*68 + col];
                unsigned bh0=__float_as_uint(y0.x), bl0=__float_as_uint(y0.y);
                unsigned bh1=__float_as_uint(y1.x), bl1=__float_as_uint(y1.y);
                #pragma unroll
                for (int i = 0; i < 2; i++) {
                    MMA8(d2[i][j], ah[i], bh0, bh1);
                    MMA8(d2[i][j], al[i], bh0, bh1);
                    MMA8(d2[i][j], ah[i], bl0, bl1);
                }
            }
        }
    }
}

// ---------------- smem tile loaders (256 threads) ----------------
// A: 128 rows x 16 cols from row-major G[lda], into k-major As[16][132]
__device__ __forceinline__ void load_A(const float* __restrict__ G, size_t lda,
                                       int m0, int k0, float2* As, int tid) {
    int r = tid >> 1, c = (tid & 1) * 8;
    const float* p = G + (size_t)(m0 + r)*lda + k0 + c;
    float4 v0 = *(const float4*)p;
    float4 v1 = *(const float4*)(p + 4);
    As[(c+0)*132 + r] = split2(v0.x);
    As[(c+1)*132 + r] = split2(v0.y);
    As[(c+2)*132 + r] = split2(v0.z);
    As[(c+3)*132 + r] = split2(v0.w);
    As[(c+4)*132 + r] = split2(v1.x);
    As[(c+5)*132 + r] = split2(v1.y);
    As[(c+6)*132 + r] = split2(v1.z);
    As[(c+7)*132 + r] = split2(v1.w);
}

// A = exp(s * G)
__device__ __forceinline__ void load_A_exp(const float* __restrict__ G, size_t lda,
                                           int m0, int k0, float2* As, int tid, float s) {
    int r = tid >> 1, c = (tid & 1) * 8;
    const float* p = G + (size_t)(m0 + r)*lda + k0 + c;
    float4 v0 = *(const float4*)p;
    float4 v1 = *(const float4*)(p + 4);
    As[(c+0)*132 + r] = split2(__expf(s*v0.x));
    As[(c+1)*132 + r] = split2(__expf(s*v0.y));
    As[(c+2)*132 + r] = split2(__expf(s*v0.z));
    As[(c+3)*132 + r] = split2(__expf(s*v0.w));
    As[(c+4)*132 + r] = split2(__expf(s*v1.x));
    As[(c+5)*132 + r] = split2(__expf(s*v1.y));
    As[(c+6)*132 + r] = split2(__expf(s*v1.z));
    As[(c+7)*132 + r] = split2(__expf(s*v1.w));
}

// A = exp(s * G + M)
__device__ __forceinline__ void load_A_expmask(const float* __restrict__ G,
                                               const float* __restrict__ Msk, size_t lda,
                                               int m0, int k0, float2* As, int tid, float s) {
    int r = tid >> 1, c = (tid & 1) * 8;
    size_t off = (size_t)(m0 + r)*lda + k0 + c;
    float4 v0 = *(const float4*)(G + off);
    float4 v1 = *(const float4*)(G + off + 4);
    float4 m0v = *(const float4*)(Msk + off);
    float4 m1v = *(const float4*)(Msk + off + 4);
    As[(c+0)*132 + r] = split2(__expf(s*v0.x + m0v.x));
    As[(c+1)*132 + r] = split2(__expf(s*v0.y + m0v.y));
    As[(c+2)*132 + r] = split2(__expf(s*v0.z + m0v.z));
    As[(c+3)*132 + r] = split2(__expf(s*v0.w + m0v.w));
    As[(c+4)*132 + r] = split2(__expf(s*v1.x + m1v.x));
    As[(c+5)*132 + r] = split2(__expf(s*v1.y + m1v.y));
    As[(c+6)*132 + r] = split2(__expf(s*v1.z + m1v.z));
    As[(c+7)*132 + r] = split2(__expf(s*v1.w + m1v.w));
}

// B: 16 k-rows x 128 cols from [k][n] global
__device__ __forceinline__ void load_B128(const float* __restrict__ G, size_t ldb,
                                          int k0, int n0, float2* Bs, int tid) {
    int k = tid >> 4, n = (tid & 15) * 8;
    const float* p = G + (size_t)(k0 + k)*ldb + n0 + n;
    float4 v0 = *(const float4*)p, v1 = *(const float4*)(p + 4);
    float2* q = Bs + k*132 + n;
    q[0] = split2(v0.x); q[1] = split2(v0.y); q[2] = split2(v0.z); q[3] = split2(v0.w);
    q[4] = split2(v1.x); q[5] = split2(v1.y); q[6] = split2(v1.z); q[7] = split2(v1.w);
}

// dual B: 16 x 64 from two [k][n] globals (ekv, ek)
__device__ __forceinline__ void load_B64x2(const float* __restrict__ G1,
                                           const float* __restrict__ G2, size_t ldb,
                                           int k0, int n0, float2* Bs1, float2* Bs2, int tid) {
    int k = tid >> 4, n = (tid & 15) * 4;
    size_t off = (size_t)(k0 + k)*ldb + n0 + n;
    float4 a = *(const float4*)(G1 + off);
    float4 b = *(const float4*)(G2 + off);
    float2* q1 = Bs1 + k*68 + n;
    float2* q2 = Bs2 + k*68 + n;
    q1[0] = split2(a.x); q1[1] = split2(a.y); q1[2] = split2(a.z); q1[3] = split2(a.w);
    q2[0] = split2(b.x); q2[1] = split2(b.y); q2[2] = split2(b.z); q2[3] = split2(b.w);
}

// B transposed: 128 n-rows of [n][k] global -> Bs[k][n]
__device__ __forceinline__ void load_Bt128(const float* __restrict__ G, size_t lda,
                                           int n0, int k0, float2* Bs, int tid) {
    int n = tid >> 1, c = (tid & 1) * 8;
    const float* p = G + (size_t)(n0 + n)*lda + k0 + c;
    float4 v0 = *(const float4*)p, v1 = *(const float4*)(p + 4);
    Bs[(c+0)*132 + n] = split2(v0.x);
    Bs[(c+1)*132 + n] = split2(v0.y);
    Bs[(c+2)*132 + n] = split2(v0.z);
    Bs[(c+3)*132 + n] = split2(v0.w);
    Bs[(c+4)*132 + n] = split2(v1.x);
    Bs[(c+5)*132 + n] = split2(v1.y);
    Bs[(c+6)*132 + n] = split2(v1.z);
    Bs[(c+7)*132 + n] = split2(v1.w);
}

// ---------------- embedding ----------------
__global__ void embed_kernel(const float* __restrict__ data,
                             const float* __restrict__ W,
                             const float* __restrict__ bias,
                             float* __restrict__ X) {
    int idx = blockIdx.x;
    int e   = threadIdx.x;
    float d0 = data[idx*2+0], d1 = data[idx*2+1];
    X[(size_t)idx*EE + e] = d0*W[e] + d1*W[EE+e] + bias[e];
}

// =====================================================================
// qkv: 3 passes (q -> SQ, k -> EK, v -> EKV via EK reload)
// =====================================================================
__global__ __launch_bounds__(256) void qkv_tc(
        const float* __restrict__ X,
        const float* __restrict__ Wq,
        const float* __restrict__ Wk,
        const float* __restrict__ Wv,
        float* __restrict__ SQ,
        float* __restrict__ EK,
        float* __restrict__ EKV) {
    __shared__ float2 As[16*132], Bs[16*132];
    const int tid = threadIdx.x, lane = tid & 31, w = tid >> 5;
    const int wr0 = (w >> 1)*32, wc0 = (w & 1)*64;
    const int qr = lane >> 2, qc = lane & 3;
    const int m0 = blockIdx.x*128;

    for (int pass = 0; pass < 3; pass++) {
        const float* Wm = (pass == 0) ? Wq : (pass == 1) ? Wk : Wv;
        float d[2][8][4] = {};
        for (int k0 = 0; k0 < EE; k0 += 16) {
            load_A(X, EE, m0, k0, As, tid);
            load_B128(Wm, EE, k0, 0, Bs, tid);
            __syncthreads();
            mma_tile_128(As, Bs, d, wr0, wc0, qr, qc);
            __syncthreads();
        }
        #pragma unroll
        for (int i = 0; i < 2; i++)
            #pragma unroll
            for (int h = 0; h < 2; h++) {
                int row = m0 + wr0 + i*16 + qr + h*8;
                #pragma unroll
                for (int j = 0; j < 8; j++) {
                    int col = wc0 + j*8 + qc*2;
                    size_t o = (size_t)row*EE + col;
                    float v0 = d[i][j][h*2], v1 = d[i][j][h*2+1];
                    if (pass == 0) {
                        *(float2*)&SQ[o] = make_float2(
                            1.f/(1.f + __expf(-v0)), 1.f/(1.f + __expf(-v1)));
                    } else if (pass == 1) {
                        *(float2*)&EK[o] = make_float2(__expf(v0), __expf(v1));
                    } else {
                        float2 e = *(const float2*)&EK[o];
                        *(float2*)&EKV[o] = make_float2(e.x*v0, e.y*v1);
                    }
                }
            }
    }
}

// =====================================================================
// dec k/v: 2 passes
// =====================================================================
__global__ __launch_bounds__(256) void deckv_tc(
        const float* __restrict__ X,
        const float* __restrict__ Wk,
        const float* __restrict__ Wv,
        float* __restrict__ EK,
        float* __restrict__ EKV) {
    __shared__ float2 As[16*132], Bs[16*132];
    const int tid = threadIdx.x, lane = tid & 31, w = tid >> 5;
    const int wr0 = (w >> 1)*32, wc0 = (w & 1)*64;
    const int qr = lane >> 2, qc = lane & 3;
    const int m0 = blockIdx.x*128;

    for (int pass = 0; pass < 2; pass++) {
        const float* Wm = (pass == 0) ? Wk : Wv;
        float d[2][8][4] = {};
        for (int k0 = 0; k0 < EE; k0 += 16) {
            load_A(X, EE, m0, k0, As, tid);
            load_B128(Wm, EE, k0, 0, Bs, tid);
            __syncthreads();
            mma_tile_128(As, Bs, d, wr0, wc0, qr, qc);
            __syncthreads();
        }
        #pragma unroll
        for (int i = 0; i < 2; i++)
            #pragma unroll
            for (int h = 0; h < 2; h++) {
                int row = m0 + wr0 + i*16 + qr + h*8;
                #pragma unroll
                for (int j = 0; j < 8; j++) {
                    int col = wc0 + j*8 + qc*2;
                    size_t o = (size_t)row*EE + col;
                    float v0 = d[i][j][h*2], v1 = d[i][j][h*2+1];
                    if (pass == 0) {
                        *(float2*)&EK[o] = make_float2(__expf(v0), __expf(v1));
                    } else {
                        float2 e = *(const float2*)&EK[o];
                        *(float2*)&EKV[o] = make_float2(e.x*v0, e.y*v1);
                    }
                }
            }
    }
}

// =====================================================================
// encoder AFT: BM=128 nodes, BN=64 of E, dual accumulation (num/den)
// =====================================================================
__global__ __launch_bounds__(256) void aft_enc_tc(
        const float* __restrict__ dist,
        const float* __restrict__ ls,
        const float* __restrict__ alpha, int l,
        const float* __restrict__ EKV,
        const float* __restrict__ EK,
        const float* __restrict__ X,
        const float* __restrict__ SQ,
        float* __restrict__ Y) {
    __shared__ float2 As[16*132], Bs1[16*68], Bs2[16*68];
    const int b = blockIdx.z;
    const int m0 = blockIdx.x*128, n0 = blockIdx.y*64;
    const float s = ls[0]*alpha[l];
    const float* D  = dist + (size_t)b*NN*NN;
    const float* B1 = EKV  + (size_t)b*NN*EE;
    const float* B2 = EK   + (size_t)b*NN*EE;
    const int tid = threadIdx.x, lane = tid & 31, w = tid >> 5;
    const int wr0 = (w >> 1)*32, wc0 = (w & 1)*32;
    const int qr = lane >> 2, qc = lane & 3;
    float d1[2][4][4] = {}, d2[2][4][4] = {};

    for (int k0 = 0; k0 < NN; k0 += 16) {
        load_A_exp(D, NN, m0, k0, As, tid, s);
        load_B64x2(B1, B2, EE, k0, n0, Bs1, Bs2, tid);
        __syncthreads();
        mma_tile_64x2(As, Bs1, Bs2, d1, d2, wr0, wc0, qr, qc);
        __syncthreads();
    }
    #pragma unroll
    for (int i = 0; i < 2; i++)
        #pragma unroll
        for (int h = 0; h < 2; h++) {
            int row = m0 + wr0 + i*16 + qr + h*8;
            #pragma unroll
            for (int j = 0; j < 4; j++) {
                int col = n0 + wc0 + j*8 + qc*2;
                size_t o = ((size_t)b*NN + row)*EE + col;
                float2 xv = *(const float2*)&X[o];
                float2 sv = *(const float2*)&SQ[o];
                float n0v = d1[i][j][h*2], n1v = d1[i][j][h*2+1];
                float de0 = d2[i][j][h*2], de1 = d2[i][j][h*2+1];
                *(float2*)&Y[o] = make_float2(
                    xv.x + sv.x*(n0v/de0), xv.y + sv.y*(n1v/de1));
            }
        }
}

// =====================================================================
// decoder AFT
// =====================================================================
__global__ __launch_bounds__(256) void dec_aft_tc(
        const float* __restrict__ cur_dist,
        const float* __restrict__ ninf,
        const float* __restrict__ ls,
        const float* __restrict__ dalpha,
        const float* __restrict__ EKV,
        const float* __restrict__ EK,
        const float* __restrict__ GQ,
        const float* __restrict__ cap,
        const float* __restrict__ dWq,
        float* __restrict__ AFT) {
    __shared__ float2 As[16*132], Bs1[16*68], Bs2[16*68];
    const int b = blockIdx.z;
    const int m0 = blockIdx.x*128, n0 = blockIdx.y*64;
    const float s = ls[0]*dalpha[0];
    const float* CD = cur_dist + (size_t)b*PP*NN;
    const float* NM = ninf     + (size_t)b*PP*NN;
    const float* B1 = EKV + (size_t)b*NN*EE;
    const float* B2 = EK  + (size_t)b*NN*EE;
    const int tid = threadIdx.x, lane = tid & 31, w = tid >> 5;
    const int wr0 = (w >> 1)*32, wc0 = (w & 1)*32;
    const int qr = lane >> 2, qc = lane & 3;
    float d1[2][4][4] = {}, d2[2][4][4] = {};

    for (int k0 = 0; k0 < NN; k0 += 16) {
        load_A_expmask(CD, NM, NN, m0, k0, As, tid, s);
        load_B64x2(B1, B2, EE, k0, n0, Bs1, Bs2, tid);
        __syncthreads();
        mma_tile_64x2(As, Bs1, Bs2, d1, d2, wr0, wc0, qr, qc);
        __syncthreads();
    }
    #pragma unroll
    for (int i = 0; i < 2; i++)
        #pragma unroll
        for (int h = 0; h < 2; h++) {
            int p = m0 + wr0 + i*16 + qr + h*8;
            float cv = cap[(size_t)b*PP + p];
            #pragma unroll
            for (int j = 0; j < 4; j++) {
                int col = n0 + wc0 + j*8 + qc*2;
                float2 gq2 = *(const float2*)&GQ[b*EE + col];
                float2 wq2 = *(const float2*)&dWq[EE*EE + col];
                float q0 = gq2.x + cv*wq2.x;
                float q1 = gq2.y + cv*wq2.y;
                float sg0 = 1.f/(1.f + __expf(-q0));
                float sg1 = 1.f/(1.f + __expf(-q1));
                float n0v = d1[i][j][h*2], n1v = d1[i][j][h*2+1];
                float de0 = d2[i][j][h*2], de1 = d2[i][j][h*2+1];
                size_t o = ((size_t)b*PP + p)*EE + col;
                *(float2*)&AFT[o] = make_float2(sg0*(n0v/de0), sg1*(n1v/de1));
            }
        }
}

// =====================================================================
// FF1: hid = relu(h@W1 + b1)
// =====================================================================
__global__ __launch_bounds__(256) void ff1_tc(
        const float* __restrict__ H,
        const float* __restrict__ W1,
        const float* __restrict__ b1,
        float* __restrict__ HID) {
    __shared__ float2 As[16*132], Bs[16*132];
    const int tid = threadIdx.x, lane = tid & 31, w = tid >> 5;
    const int wr0 = (w >> 1)*32, wc0 = (w & 1)*64;
    const int qr = lane >> 2, qc = lane & 3;
    const int m0 = blockIdx.x*128, n0 = blockIdx.y*128;
    float d[2][8][4] = {};

    for (int k0 = 0; k0 < EE; k0 += 16) {
        load_A(H, EE, m0, k0, As, tid);
        load_B128(W1, FFD, k0, n0, Bs, tid);
        __syncthreads();
        mma_tile_128(As, Bs, d, wr0, wc0, qr, qc);
        __syncthreads();
    }
    #pragma unroll
    for (int i = 0; i < 2; i++)
        #pragma unroll
        for (int h = 0; h < 2; h++) {
            int row = m0 + wr0 + i*16 + qr + h*8;
            #pragma unroll
            for (int j = 0; j < 8; j++) {
                int col = n0 + wc0 + j*8 + qc*2;
                float2 bb = *(const float2*)&b1[col];
                size_t o = (size_t)row*FFD + col;
                *(float2*)&HID[o] = make_float2(
                    fmaxf(d[i][j][h*2]   + bb.x, 0.f),
                    fmaxf(d[i][j][h*2+1] + bb.y, 0.f));
            }
        }
}

// =====================================================================
// FF2: y = h + hid@W2 + b2   (K=512, N=128)
// =====================================================================
__global__ __launch_bounds__(256) void ff2_tc(
        const float* __restrict__ HID,
        const float* __restrict__ W2,
        const float* __restrict__ b2,
        const float* __restrict__ H,
        float* __restrict__ Y) {
    __shared__ float2 As[16*132], Bs[16*132];
    const int tid = threadIdx.x, lane = tid & 31, w = tid >> 5;
    const int wr0 = (w >> 1)*32, wc0 = (w & 1)*64;
    const int qr = lane >> 2, qc = lane & 3;
    const int m0 = blockIdx.x*128;
    float d[2][8][4] = {};

    for (int k0 = 0; k0 < FFD; k0 += 16) {
        load_A(HID, FFD, m0, k0, As, tid);
        load_B128(W2, EE, k0, 0, Bs, tid);
        __syncthreads();
        mma_tile_128(As, Bs, d, wr0, wc0, qr, qc);
        __syncthreads();
    }
    #pragma unroll
    for (int i = 0; i < 2; i++)
        #pragma unroll
        for (int h = 0; h < 2; h++) {
            int row = m0 + wr0 + i*16 + qr + h*8;
            #pragma unroll
            for (int j = 0; j < 8; j++) {
                int col = wc0 + j*8 + qc*2;
                float2 bb = *(const float2*)&b2[col];
                size_t o = (size_t)row*EE + col;
                float2 hv = *(const float2*)&H[o];
                *(float2*)&Y[o] = make_float2(
                    hv.x + d[i][j][h*2]   + bb.x,
                    hv.y + d[i][j][h*2+1] + bb.y);
            }
        }
}

// =====================================================================
// score: S = aft @ enc^T + epilogue (K=128)
// =====================================================================
__global__ __launch_bounds__(256) void score_tc(
        const float* __restrict__ AFT,
        const float* __restrict__ ENC,
        const float* __restrict__ cur_dist,
        const float* __restrict__ ninf,
        const float* __restrict__ ls,
        const float* __restrict__ palpha,
        float* __restrict__ OUT) {
    __shared__ float2 As[16*132], Bs[16*132];
    const int b = blockIdx.z;
    const int p0 = blockIdx.x*128, n0 = blockIdx.y*128;
    const float ps = ls[0]*palpha[0];
    const float* A  = AFT + (size_t)b*PP*EE;
    const float* Eb = ENC + (size_t)b*NN*EE;
    const int tid = threadIdx.x, lane = tid & 31, w = tid >> 5;
    const int wr0 = (w >> 1)*32, wc0 = (w & 1)*64;
    const int qr = lane >> 2, qc = lane & 3;
    float d[2][8][4] = {};

    for (int k0 = 0; k0 < EE; k0 += 16) {
        load_A(A, EE, p0, k0, As, tid);
        load_Bt128(Eb, EE, n0, k0, Bs, tid);
        __syncthreads();
        mma_tile_128(As, Bs, d, wr0, wc0, qr, qc);
        __syncthreads();
    }
    #pragma unroll
    for (int i = 0; i < 2; i++)
        #pragma unroll
        for (int h = 0; h < 2; h++) {
            int p = p0 + wr0 + i*16 + qr + h*8;
            #pragma unroll
            for (int j = 0; j < 8; j++) {
                int n = n0 + wc0 + j*8 + qc*2;
                size_t o = ((size_t)b*PP + p)*NN + n;
                float2 cd = *(const float2*)&cur_dist[o];
                float2 nm = *(const float2*)&ninf[o];
                float s0 = d[i][j][h*2]  *INV_SQRT_E + ps*cd.x;
                float s1 = d[i][j][h*2+1]*INV_SQRT_E + ps*cd.y;
                *(float2*)&OUT[o] = make_float2(
                    10.f*tanhf(s0) + nm.x, 10.f*tanhf(s1) + nm.y);
            }
        }
}

// ---------------- instance norm over node dim (axis=1) ----------------
__global__ void inorm_kernel(const float* __restrict__ src,
                             float* __restrict__ dst,
                             const float* __restrict__ w,
                             const float* __restrict__ bias) {
    int b = blockIdx.x;
    int e = threadIdx.x;
    int c = threadIdx.y;
    const float* S = src + (size_t)b*NN*EE;
    float s = 0.f, s2 = 0.f;
    for (int n = c*64; n < c*64 + 64; n++) {
        float v = S[(size_t)n*EE + e];
        s += v; s2 += v*v;
    }
    __shared__ float ssum[8][128], ssq[8][128];
    __shared__ float smu[128], srs[128];
    ssum[c][e] = s; ssq[c][e] = s2;
    __syncthreads();
    if (c == 0) {
        float ts = 0.f, t2 = 0.f;
        #pragma unroll
        for (int i = 0; i < 8; i++) { ts += ssum[i][e]; t2 += ssq[i][e]; }
        float mu = ts*(1.f/NN);
        float var = t2*(1.f/NN) - mu*mu;
        smu[e] = mu;
        srs[e] = rsqrtf(var + EPS);
    }
    __syncthreads();
    float mu = smu[e], rs = srs[e], ww = w[e], bb = bias[e];
    float* Dd = dst + (size_t)b*NN*EE;
    for (int n = c*64; n < c*64 + 64; n++) {
        size_t o = (size_t)n*EE + e;
        Dd[o] = (S[o] - mu)*rs*ww + bb;
    }
}

// ---------------- graph mean over nodes ----------------
__global__ void gmean_kernel(const float* __restrict__ X, float* __restrict__ GM) {
    int b = blockIdx.x, e = threadIdx.x, c = threadIdx.y;
    float s = 0.f;
    for (int n = c*64; n < c*64 + 64; n++)
        s += X[((size_t)b*NN + n)*EE + e];
    __shared__ float sm[8][128];
    sm[c][e] = s;
    __syncthreads();
    if (c == 0) {
        float t = 0.f;
        #pragma unroll
        for (int i = 0; i < 8; i++) t += sm[i][e];
        GM[b*EE + e] = t*(1.f/NN);
    }
}

// ---------------- gq = gmean @ dWq[0:E,:] ----------------
__global__ void gq_kernel(const float* __restrict__ GM,
                          const float* __restrict__ dWq,
                          float* __restrict__ GQ) {
    int b = blockIdx.x, e = threadIdx.x;
    float acc = 0.f;
    for (int i = 0; i < EE; i++)
        acc += GM[b*EE + i]*dWq[i*EE + e];
    GQ[b*EE + e] = acc;
}

// ---------------- row softmax over last dim (512) ----------------
__global__ void softmax_kernel(float* __restrict__ OUT) {
    float* row = OUT + (size_t)blockIdx.x*NN;
    int t = threadIdx.x;
    float v[4];
    #pragma unroll
    for (int i = 0; i < 4; i++) v[i] = row[t + i*128];
    float m = fmaxf(fmaxf(v[0], v[1]), fmaxf(v[2], v[3]));
    __shared__ float red[4];
    #pragma unroll
    for (int off = 16; off > 0; off >>= 1)
        m = fmaxf(m, __shfl_xor_sync(0xffffffff, m, off));
    if ((t & 31) == 0) red[t >> 5] = m;
    __syncthreads();
    m = fmaxf(fmaxf(red[0], red[1]), fmaxf(red[2], red[3]));
    __syncthreads();
    float s = 0.f;
    #pragma unroll
    for (int i = 0; i < 4; i++) { v[i] = __expf(v[i] - m); s += v[i]; }
    #pragma unroll
    for (int off = 16; off > 0; off >>= 1)
        s += __shfl_xor_sync(0xffffffff, s, off);
    if ((t & 31) == 0) red[t >> 5] = s;
    __syncthreads();
    s = red[0] + red[1] + red[2] + red[3];
    float inv = 1.f/s;
    #pragma unroll
    for (int i = 0; i < 4; i++) row[t + i*128] = v[i]*inv;
}

// ---------------- launch ----------------
extern "C" void kernel_launch(void* const* d_in, const int* in_sizes, int n_in,
                              void* d_out, int out_size) {
    const float* data      = (const float*)d_in[0];
    const float* dist      = (const float*)d_in[1];
    const float* cur_dist  = (const float*)d_in[2];
    const float* capacity  = (const float*)d_in[3];
    const float* ninf_mask = (const float*)d_in[4];
    const float* log_scale = (const float*)d_in[5];
    const float* emb_W     = (const float*)d_in[6];
    const float* emb_b     = (const float*)d_in[7];
    const float* Wq        = (const float*)d_in[8];
    const float* Wk        = (const float*)d_in[9];
    const float* Wv        = (const float*)d_in[10];
    const float* aft_alpha = (const float*)d_in[11];
    const float* n1_w      = (const float*)d_in[12];
    const float* n1_b      = (const float*)d_in[13];
    const float* ff_W1     = (const float*)d_in[14];
    const float* ff_b1     = (const float*)d_in[15];
    const float* ff_W2     = (const float*)d_in[16];
    const float* ff_b2     = (const float*)d_in[17];
    const float* n2_w      = (const float*)d_in[18];
    const float* n2_b      = (const float*)d_in[19];
    const float* dWq       = (const float*)d_in[20];
    const float* dWk       = (const float*)d_in[21];
    const float* dWv       = (const float*)d_in[22];
    const float* dec_alpha = (const float*)d_in[23];
    const float* p_alpha   = (const float*)d_in[24];
    float* out = (float*)d_out;

    float *x, *y, *h, *sq, *ek, *ekv, *hid, *aft, *gq, *gm;
    cudaGetSymbolAddress((void**)&x,   g_x);
    cudaGetSymbolAddress((void**)&y,   g_y);
    cudaGetSymbolAddress((void**)&h,   g_h);
    cudaGetSymbolAddress((void**)&sq,  g_sq);
    cudaGetSymbolAddress((void**)&ek,  g_ek);
    cudaGetSymbolAddress((void**)&ekv, g_ekv);
    cudaGetSymbolAddress((void**)&hid, g_hid);
    cudaGetSymbolAddress((void**)&aft, g_aft);
    cudaGetSymbolAddress((void**)&gq,  g_gq);
    cudaGetSymbolAddress((void**)&gm,  g_gm);

    embed_kernel<<<M_TOT, EE>>>(data, emb_W, emb_b, x);

    for (int l = 0; l < LLAYERS; l++) {
        qkv_tc<<<M_TOT/128, 256>>>(
            x, Wq + (size_t)l*EE*EE, Wk + (size_t)l*EE*EE, Wv + (size_t)l*EE*EE,
            sq, ek, ekv);
        aft_enc_tc<<<dim3(NN/128, EE/64, BB), 256>>>(
            dist, log_scale, aft_alpha, l, ekv, ek, x, sq, y);
        inorm_kernel<<<BB, dim3(128, 8)>>>(y, h, n1_w + l*EE, n1_b + l*EE);
        ff1_tc<<<dim3(M_TOT/128, FFD/128), 256>>>(
            h, ff_W1 + (size_t)l*EE*FFD, ff_b1 + l*FFD, hid);
        ff2_tc<<<M_TOT/128, 256>>>(
            hid, ff_W2 + (size_t)l*FFD*EE, ff_b2 + l*EE, h, y);
        inorm_kernel<<<BB, dim3(128, 8)>>>(y, x, n2_w + l*EE, n2_b + l*EE);
    }

    // decoder
    deckv_tc<<<M_TOT/128, 256>>>(x, dWk, dWv, ek, ekv);
    gmean_kernel<<<BB, dim3(128, 8)>>>(x, gm);
    gq_kernel<<<BB, 128>>>(gm, dWq, gq);
    dec_aft_tc<<<dim3(PP/128, EE/64, BB), 256>>>(
        cur_dist, ninf_mask, log_scale, dec_alpha, ekv, ek, gq, capacity, dWq, aft);
    score_tc<<<dim3(PP/128, NN/128, BB), 256>>>(
        aft, x, cur_dist, ninf_mask, log_scale, p_alpha, out);
    softmax_kernel<<<BB*PP, 128>>>(out);
}